// round 3
// baseline (speedup 1.0000x reference)
#include <cuda_runtime.h>
#include <cuda_bf16.h>

// Problem constants (fixed by the dataset)
#define NN 50000
#define DH 128
#define EE 800000

// Scratch (static device globals — no allocation at launch time).
// NOTE: these must ONLY be referenced from device code; passing them as
// kernel arguments from host code yields the host shadow address (bug found
// in rounds 1-2).
__device__ float g_rh [NN * DH];   // r * h_prev
__device__ float g_z  [NN * DH];   // update gate
__device__ float g_y  [NN * DH];   // xc @ W_l   (pre-aggregation)
__device__ float g_w  [NN * DH];   // xc @ W_r
__device__ float g_agg[NN * DH];   // segment_sum of y[src]
__device__ float g_cnt[NN];        // in-degree

__device__ __forceinline__ float sigmoidf_(float v) {
    return 1.0f / (1.0f + __expf(-v));
}

// ---------------------------------------------------------------------------
// Fused SGEMM: C[N,128] = [A0 | A1] (N x 256) @ [Btop ; Bbot] (256 x 128)
// MODE 0: A1 = hprev;  sigmoid(acc + bias) * h_prev -> g_rh
// MODE 1: A1 = hprev;  sigmoid(acc + bias)          -> g_z
// MODE 2: A1 = g_rh (device global); acc            -> g_y
// MODE 3: A1 = g_rh (device global); acc            -> g_w
// Tiling: BM=128, BN=128, BK=8, 256 threads, 8x8 per thread.
// ---------------------------------------------------------------------------
template <int MODE>
__global__ __launch_bounds__(256) void gemm_fused(
    const float* __restrict__ A0, const float* __restrict__ A1p,
    const float* __restrict__ Btop, const float* __restrict__ Bbot,
    const float* __restrict__ bias, const float* __restrict__ hprev,
    int Nrows)
{
    __shared__ __align__(16) float As[8][128];
    __shared__ __align__(16) float Bs[8][128];

    // Resolve the second A operand IN DEVICE CODE so device globals get the
    // correct device address.
    const float* A1 = (MODE >= 2) ? (const float*)g_rh : A1p;

    const int tid  = threadIdx.x;
    const int row0 = blockIdx.x * 128;
    const int tx   = tid & 15;          // 0..15 (col groups of 8)
    const int ty   = tid >> 4;          // 0..15 (row groups of 8)

    // A-tile load mapping: 128 rows x 8 cols = 256 float4 (transposed store)
    const int aRow = tid >> 1;          // 0..127
    const int aCol = (tid & 1) * 4;     // 0 or 4
    // B-tile load mapping: 8 rows x 128 cols = 256 float4
    const int bRow = tid >> 5;          // 0..7
    const int bCol = (tid & 31) * 4;    // 0..124

    float acc[8][8];
#pragma unroll
    for (int i = 0; i < 8; i++)
#pragma unroll
        for (int j = 0; j < 8; j++) acc[i][j] = 0.0f;

    for (int k0 = 0; k0 < 256; k0 += 8) {
        // stage loads to registers
        float4 av = make_float4(0.f, 0.f, 0.f, 0.f);
        const int gr = row0 + aRow;
        if (gr < Nrows) {
            const float* Asrc = (k0 < 128) ? A0 : A1;
            av = *(const float4*)&Asrc[(size_t)gr * DH + (k0 & 127) + aCol];
        }
        const float* Bsrc = (k0 < 128) ? Btop : Bbot;
        const float4 bv = *(const float4*)&Bsrc[(size_t)((k0 & 127) + bRow) * DH + bCol];

        __syncthreads();   // previous tile fully consumed
        As[aCol + 0][aRow] = av.x;
        As[aCol + 1][aRow] = av.y;
        As[aCol + 2][aRow] = av.z;
        As[aCol + 3][aRow] = av.w;
        *(float4*)&Bs[bRow][bCol] = bv;
        __syncthreads();

#pragma unroll
        for (int k = 0; k < 8; k++) {
            float a[8], b[8];
            const float4 a0 = *(const float4*)&As[k][ty * 8];
            const float4 a1 = *(const float4*)&As[k][ty * 8 + 4];
            const float4 b0 = *(const float4*)&Bs[k][tx * 8];
            const float4 b1 = *(const float4*)&Bs[k][tx * 8 + 4];
            a[0]=a0.x; a[1]=a0.y; a[2]=a0.z; a[3]=a0.w;
            a[4]=a1.x; a[5]=a1.y; a[6]=a1.z; a[7]=a1.w;
            b[0]=b0.x; b[1]=b0.y; b[2]=b0.z; b[3]=b0.w;
            b[4]=b1.x; b[5]=b1.y; b[6]=b1.z; b[7]=b1.w;
#pragma unroll
            for (int i = 0; i < 8; i++)
#pragma unroll
                for (int j = 0; j < 8; j++)
                    acc[i][j] = fmaf(a[i], b[j], acc[i][j]);
        }
    }

    // epilogue
#pragma unroll
    for (int i = 0; i < 8; i++) {
        const int gr = row0 + ty * 8 + i;
        if (gr >= Nrows) continue;
#pragma unroll
        for (int jj = 0; jj < 8; jj += 4) {
            const int col = tx * 8 + jj;
            float4 v = make_float4(acc[i][jj], acc[i][jj + 1],
                                   acc[i][jj + 2], acc[i][jj + 3]);
            if (MODE < 2) {
                const float4 b = *(const float4*)&bias[col];
                v.x = sigmoidf_(v.x + b.x);
                v.y = sigmoidf_(v.y + b.y);
                v.z = sigmoidf_(v.z + b.z);
                v.w = sigmoidf_(v.w + b.w);
            }
            const size_t off = (size_t)gr * DH + col;
            if (MODE == 0) {
                const float4 hh = *(const float4*)&hprev[off];
                v.x *= hh.x; v.y *= hh.y; v.z *= hh.z; v.w *= hh.w;
                *(float4*)&g_rh[off] = v;
            } else if (MODE == 1) {
                *(float4*)&g_z[off] = v;
            } else if (MODE == 2) {
                *(float4*)&g_y[off] = v;
            } else {
                *(float4*)&g_w[off] = v;
            }
        }
    }
}

// ---------------------------------------------------------------------------
// Zero accumulators
// ---------------------------------------------------------------------------
__global__ void zero_kernel()
{
    const int i = blockIdx.x * blockDim.x + threadIdx.x;
    const int n4 = NN * (DH / 4);
    if (i < n4) {
        *(float4*)&g_agg[(size_t)i * 4] = make_float4(0.f, 0.f, 0.f, 0.f);
    }
    if (i < NN) g_cnt[i] = 0.0f;
}

// ---------------------------------------------------------------------------
// Edge scatter: one warp per edge; lane l handles floats [4l, 4l+4).
// Vectorized no-return global reduction (validated: produced bit-comparable
// aggregation to scalar atomicAdd in rounds 1 vs 2).
// ---------------------------------------------------------------------------
__global__ __launch_bounds__(256) void scatter_kernel(const int* __restrict__ ei)
{
    const int warp = (blockIdx.x * blockDim.x + threadIdx.x) >> 5;
    const int lane = threadIdx.x & 31;
    if (warp >= EE) return;

    const int src = ei[warp];
    const int dst = ei[EE + warp];

    const float4 v = *(const float4*)&g_y[(size_t)src * DH + lane * 4];
    float* p = &g_agg[(size_t)dst * DH + lane * 4];
    asm volatile("red.global.add.v4.f32 [%0], {%1,%2,%3,%4};"
                 :: "l"(p), "f"(v.x), "f"(v.y), "f"(v.z), "f"(v.w)
                 : "memory");
    if (lane == 0) {
        asm volatile("red.global.add.f32 [%0], %1;"
                     :: "l"(&g_cnt[dst]), "f"(1.0f) : "memory");
    }
}

// ---------------------------------------------------------------------------
// Final: out = (1-z) * (agg/max(cnt,1) + b_l + w) + z * h_prev
// ---------------------------------------------------------------------------
__global__ __launch_bounds__(256) void final_kernel(
    const float* __restrict__ hprev, const float* __restrict__ b_l,
    float* __restrict__ out)
{
    const int i4 = blockIdx.x * blockDim.x + threadIdx.x;   // over NN*32
    if (i4 >= NN * (DH / 4)) return;
    const int node = i4 >> 5;
    const int c4   = i4 & 31;
    const size_t off = (size_t)i4 * 4;

    const float inv = 1.0f / fmaxf(g_cnt[node], 1.0f);
    const float4 a  = *(const float4*)&g_agg[off];
    const float4 w  = *(const float4*)&g_w[off];
    const float4 z  = *(const float4*)&g_z[off];
    const float4 hh = *(const float4*)&hprev[off];
    const float4 bl = *(const float4*)&b_l[c4 * 4];

    float4 o;
    float n;
    n = fmaf(a.x, inv, bl.x) + w.x; o.x = (1.0f - z.x) * n + z.x * hh.x;
    n = fmaf(a.y, inv, bl.y) + w.y; o.y = (1.0f - z.y) * n + z.y * hh.y;
    n = fmaf(a.z, inv, bl.z) + w.z; o.z = (1.0f - z.z) * n + z.z * hh.z;
    n = fmaf(a.w, inv, bl.w) + w.w; o.w = (1.0f - z.w) * n + z.w * hh.w;
    *(float4*)&out[off] = o;
}

// ---------------------------------------------------------------------------
extern "C" void kernel_launch(void* const* d_in, const int* in_sizes, int n_in,
                              void* d_out, int out_size)
{
    const float* x    = (const float*)d_in[0];
    const int*   ei   = (const int*)  d_in[1];
    const float* h    = (const float*)d_in[2];
    const float* W_xr = (const float*)d_in[3];
    const float* b_xr = (const float*)d_in[4];
    const float* W_hr = (const float*)d_in[5];
    const float* W_xz = (const float*)d_in[6];
    const float* b_xz = (const float*)d_in[7];
    const float* W_hz = (const float*)d_in[8];
    const float* W_l  = (const float*)d_in[9];
    const float* b_l  = (const float*)d_in[10];
    const float* W_r  = (const float*)d_in[11];
    float* out = (float*)d_out;

    const int gemm_grid = (NN + 127) / 128;   // 391

    // zero accumulators (independent of GEMMs; run first)
    {
        const int n = NN * (DH / 4);
        zero_kernel<<<(n + 255) / 256, 256>>>();
    }

    // Gates: r (-> g_rh = sigmoid(..)*h), z (-> g_z)
    gemm_fused<0><<<gemm_grid, 256>>>(x, h, W_xr, W_hr, b_xr, h, NN);
    gemm_fused<1><<<gemm_grid, 256>>>(x, h, W_xz, W_hz, b_xz, h, NN);

    // Candidate projections: y = xc@W_l (-> g_y), w = xc@W_r (-> g_w)
    // A1 (= g_rh) is resolved inside device code; the pointer arg is unused.
    gemm_fused<2><<<gemm_grid, 256>>>(x, nullptr, W_l, W_l + 128 * DH, nullptr, h, NN);
    gemm_fused<3><<<gemm_grid, 256>>>(x, nullptr, W_r, W_r + 128 * DH, nullptr, h, NN);

    // Edge scatter: one warp per edge -> (EE warps) / 8 warps per block
    scatter_kernel<<<(EE + 7) / 8, 256>>>(ei);

    // Final combine
    final_kernel<<<(NN * (DH / 4) + 255) / 256, 256>>>(h, b_l, out);
}

// round 4
// speedup vs baseline: 2.0911x; 2.0911x over previous
#include <cuda_runtime.h>
#include <cstdint>

// Problem constants (fixed by the dataset)
#define NN 50000
#define DH 128
#define EE 800000
#define KK 256

// ---------------------------------------------------------------------------
// Scratch device globals. Referenced ONLY from device code (host-shadow bug!).
// ---------------------------------------------------------------------------
__device__ uint32_t g_x32 [NN * DH];     // tf32(x)
__device__ uint32_t g_h32 [NN * DH];     // tf32(h_prev)
__device__ uint32_t g_rh32[NN * DH];     // tf32(r * h_prev)
__device__ uint32_t g_WB  [4 * KK * DH]; // packed tf32 weights, one 256x128 per GEMM
__device__ float g_z  [NN * DH];
__device__ float g_y  [NN * DH];
__device__ float g_w  [NN * DH];
__device__ float g_agg[NN * DH];
__device__ float g_cnt[NN];

__device__ __forceinline__ float sigmoidf_(float v) {
    return 1.0f / (1.0f + __expf(-v));
}
__device__ __forceinline__ uint32_t f2tf32(float f) {
    uint32_t r;
    asm("cvt.rna.tf32.f32 %0, %1;" : "=r"(r) : "f"(f));
    return r;
}
__device__ __forceinline__ void cpasync16(uint32_t dst, const void* src, int sz) {
    asm volatile("cp.async.ca.shared.global [%0], [%1], 16, %2;"
                 :: "r"(dst), "l"(src), "r"(sz));
}
__device__ __forceinline__ void mma_tf32(float c[4], uint32_t a0, uint32_t a1,
                                         uint32_t a2, uint32_t a3,
                                         uint32_t b0, uint32_t b1) {
    asm volatile(
        "mma.sync.aligned.m16n8k8.row.col.f32.tf32.tf32.f32 "
        "{%0,%1,%2,%3}, {%4,%5,%6,%7}, {%8,%9}, {%0,%1,%2,%3};"
        : "+f"(c[0]), "+f"(c[1]), "+f"(c[2]), "+f"(c[3])
        : "r"(a0), "r"(a1), "r"(a2), "r"(a3), "r"(b0), "r"(b1));
}

// ---------------------------------------------------------------------------
// Prep: pack weights as tf32 into g_WB.
//   mode 0: [W_xr ; W_hr]   mode 1: [W_xz ; W_hz]   mode 2: W_l   mode 3: W_r
// ---------------------------------------------------------------------------
__global__ __launch_bounds__(256) void prep_w(
    const float* __restrict__ W_xr, const float* __restrict__ W_hr,
    const float* __restrict__ W_xz, const float* __restrict__ W_hz,
    const float* __restrict__ W_l,  const float* __restrict__ W_r)
{
    const int i = blockIdx.x * blockDim.x + threadIdx.x;  // over KK*DH = 32768
    if (i >= KK * DH) return;
    const int k = i / DH;
    const int n = i % DH;
    const int kl = (k & 127) * DH + n;
    g_WB[0 * KK * DH + i] = f2tf32(k < 128 ? W_xr[kl] : W_hr[kl]);
    g_WB[1 * KK * DH + i] = f2tf32(k < 128 ? W_xz[kl] : W_hz[kl]);
    g_WB[2 * KK * DH + i] = f2tf32(W_l[i]);
    g_WB[3 * KK * DH + i] = f2tf32(W_r[i]);
}

// Prep: convert x and h to tf32 (rna), also zero g_agg / g_cnt.
__global__ __launch_bounds__(256) void prep_xh(
    const float* __restrict__ x, const float* __restrict__ h)
{
    const int i = blockIdx.x * blockDim.x + threadIdx.x;  // over NN*DH/4
    if (i >= NN * (DH / 4)) return;
    const float4 xv = *(const float4*)&x[(size_t)i * 4];
    const float4 hv = *(const float4*)&h[(size_t)i * 4];
    uint4 xo, ho;
    xo.x = f2tf32(xv.x); xo.y = f2tf32(xv.y); xo.z = f2tf32(xv.z); xo.w = f2tf32(xv.w);
    ho.x = f2tf32(hv.x); ho.y = f2tf32(hv.y); ho.z = f2tf32(hv.z); ho.w = f2tf32(hv.w);
    *(uint4*)&g_x32[(size_t)i * 4] = xo;
    *(uint4*)&g_h32[(size_t)i * 4] = ho;
    *(float4*)&g_agg[(size_t)i * 4] = make_float4(0.f, 0.f, 0.f, 0.f);
    if (i < NN) g_cnt[i] = 0.0f;
}

// ---------------------------------------------------------------------------
// TF32 tensor-core GEMM: C[N,128] = Acat[N,256] @ B[256,128]
//   MODE 0: Acat=[x|h],  epi: rh = sigmoid(c+bias)*h -> g_rh32 (tf32)
//   MODE 1: Acat=[x|h],  epi: z  = sigmoid(c+bias)   -> g_z (f32)
//   MODE 2: Acat=[x|rh], epi: c -> g_y
//   MODE 3: Acat=[x|rh], epi: c -> g_w
// BM=128 BN=128 BK=16, 256 threads, warp tile 64x32, cp.async double buffer.
// ---------------------------------------------------------------------------
#define AP 20    // As row pitch in words (bank-conflict-free)
#define BP 136   // Bs row pitch in words

template <int MODE>
__global__ __launch_bounds__(256) void gemm_tf32(
    const float* __restrict__ bias, const float* __restrict__ hprev, int Nrows)
{
    __shared__ uint32_t As[2][128 * AP];
    __shared__ uint32_t Bs[2][16 * BP];

    const uint32_t* A0 = g_x32;
    const uint32_t* A1 = (MODE >= 2) ? g_rh32 : g_h32;
    const uint32_t* B  = g_WB + MODE * (KK * DH);

    const int tid  = threadIdx.x;
    const int lane = tid & 31;
    const int wid  = tid >> 5;
    const int row0 = blockIdx.x * 128;
    const int wm   = (wid >> 2) * 64;   // warp m offset (0 / 64)
    const int wn   = (wid & 3) * 32;    // warp n offset (0/32/64/96)
    const int g    = lane >> 2;         // 0..7
    const int t    = lane & 3;          // 0..3

    float acc[4][4][4];
#pragma unroll
    for (int mi = 0; mi < 4; mi++)
#pragma unroll
        for (int ni = 0; ni < 4; ni++)
#pragma unroll
            for (int q = 0; q < 4; q++) acc[mi][ni][q] = 0.0f;

    // staging: issue cp.async for K-chunk c into buffer buf
    auto stage = [&](int c, int buf) {
        const int k0 = c * 16;
        const uint32_t* Asrc = (k0 < 128) ? A0 : A1;
        const int ka = k0 & 127;
#pragma unroll
        for (int i = 0; i < 2; i++) {           // A: 128 rows x 16 = 512 float4
            const int id  = tid + i * 256;
            const int row = id >> 2;
            const int kq  = (id & 3) * 4;
            const uint32_t dst = (uint32_t)__cvta_generic_to_shared(
                &As[buf][row * AP + kq]);
            const int sz = (row0 + row < Nrows) ? 16 : 0;
            cpasync16(dst, &Asrc[(size_t)(row0 + row) * DH + ka + kq], sz);
        }
#pragma unroll
        for (int i = 0; i < 2; i++) {           // B: 16 rows x 128 = 512 float4
            const int id  = tid + i * 256;
            const int row = id >> 5;
            const int nq  = (id & 31) * 4;
            const uint32_t dst = (uint32_t)__cvta_generic_to_shared(
                &Bs[buf][row * BP + nq]);
            cpasync16(dst, &B[(size_t)(k0 + row) * DH + nq], 16);
        }
        asm volatile("cp.async.commit_group;");
    };

    stage(0, 0);

#pragma unroll 1
    for (int c = 0; c < 16; c++) {
        if (c < 15) {
            stage(c + 1, (c + 1) & 1);
            asm volatile("cp.async.wait_group %0;" :: "n"(1));
        } else {
            asm volatile("cp.async.wait_group %0;" :: "n"(0));
        }
        __syncthreads();

        const int buf = c & 1;
#pragma unroll
        for (int k8 = 0; k8 < 2; k8++) {
            const int kk = k8 * 8;
            uint32_t a[4][4], b[4][2];
#pragma unroll
            for (int mi = 0; mi < 4; mi++) {
                const int rb = wm + mi * 16 + g;
                a[mi][0] = As[buf][(rb)     * AP + kk + t];
                a[mi][1] = As[buf][(rb + 8) * AP + kk + t];
                a[mi][2] = As[buf][(rb)     * AP + kk + t + 4];
                a[mi][3] = As[buf][(rb + 8) * AP + kk + t + 4];
            }
#pragma unroll
            for (int ni = 0; ni < 4; ni++) {
                const int cb = wn + ni * 8 + g;
                b[ni][0] = Bs[buf][(kk + t)     * BP + cb];
                b[ni][1] = Bs[buf][(kk + t + 4) * BP + cb];
            }
#pragma unroll
            for (int mi = 0; mi < 4; mi++)
#pragma unroll
                for (int ni = 0; ni < 4; ni++)
                    mma_tf32(acc[mi][ni], a[mi][0], a[mi][1], a[mi][2], a[mi][3],
                             b[ni][0], b[ni][1]);
        }
        __syncthreads();
    }

    // epilogue: thread owns (row = wm+mi*16+g(+8), cols = wn+ni*8+2t, +1)
#pragma unroll
    for (int mi = 0; mi < 4; mi++) {
#pragma unroll
        for (int half = 0; half < 2; half++) {
            const int grow = row0 + wm + mi * 16 + g + half * 8;
            if (grow >= Nrows) continue;
#pragma unroll
            for (int ni = 0; ni < 4; ni++) {
                const int col = wn + ni * 8 + 2 * t;
                float c0 = acc[mi][ni][half * 2 + 0];
                float c1 = acc[mi][ni][half * 2 + 1];
                const size_t off = (size_t)grow * DH + col;
                if (MODE == 0) {
                    c0 = sigmoidf_(c0 + bias[col]);
                    c1 = sigmoidf_(c1 + bias[col + 1]);
                    const float2 hh = *(const float2*)&hprev[off];
                    uint2 o;
                    o.x = f2tf32(c0 * hh.x);
                    o.y = f2tf32(c1 * hh.y);
                    *(uint2*)&g_rh32[off] = o;
                } else if (MODE == 1) {
                    float2 o;
                    o.x = sigmoidf_(c0 + bias[col]);
                    o.y = sigmoidf_(c1 + bias[col + 1]);
                    *(float2*)&g_z[off] = o;
                } else if (MODE == 2) {
                    *(float2*)&g_y[off] = make_float2(c0, c1);
                } else {
                    *(float2*)&g_w[off] = make_float2(c0, c1);
                }
            }
        }
    }
}

// ---------------------------------------------------------------------------
// Edge scatter: one warp per edge; lane l handles floats [4l, 4l+4).
// ---------------------------------------------------------------------------
__global__ __launch_bounds__(256) void scatter_kernel(const int* __restrict__ ei)
{
    const int warp = (blockIdx.x * blockDim.x + threadIdx.x) >> 5;
    const int lane = threadIdx.x & 31;
    if (warp >= EE) return;

    const int src = ei[warp];
    const int dst = ei[EE + warp];

    const float4 v = *(const float4*)&g_y[(size_t)src * DH + lane * 4];
    float* p = &g_agg[(size_t)dst * DH + lane * 4];
    asm volatile("red.global.add.v4.f32 [%0], {%1,%2,%3,%4};"
                 :: "l"(p), "f"(v.x), "f"(v.y), "f"(v.z), "f"(v.w)
                 : "memory");
    if (lane == 0) {
        asm volatile("red.global.add.f32 [%0], %1;"
                     :: "l"(&g_cnt[dst]), "f"(1.0f) : "memory");
    }
}

// ---------------------------------------------------------------------------
// Final: out = (1-z) * (agg/max(cnt,1) + b_l + w) + z * h_prev
// ---------------------------------------------------------------------------
__global__ __launch_bounds__(256) void final_kernel(
    const float* __restrict__ hprev, const float* __restrict__ b_l,
    float* __restrict__ out)
{
    const int i4 = blockIdx.x * blockDim.x + threadIdx.x;   // over NN*32
    if (i4 >= NN * (DH / 4)) return;
    const int node = i4 >> 5;
    const int c4   = i4 & 31;
    const size_t off = (size_t)i4 * 4;

    const float inv = 1.0f / fmaxf(g_cnt[node], 1.0f);
    const float4 a  = *(const float4*)&g_agg[off];
    const float4 w  = *(const float4*)&g_w[off];
    const float4 z  = *(const float4*)&g_z[off];
    const float4 hh = *(const float4*)&hprev[off];
    const float4 bl = *(const float4*)&b_l[c4 * 4];

    float4 o;
    float n;
    n = fmaf(a.x, inv, bl.x) + w.x; o.x = (1.0f - z.x) * n + z.x * hh.x;
    n = fmaf(a.y, inv, bl.y) + w.y; o.y = (1.0f - z.y) * n + z.y * hh.y;
    n = fmaf(a.z, inv, bl.z) + w.z; o.z = (1.0f - z.z) * n + z.z * hh.z;
    n = fmaf(a.w, inv, bl.w) + w.w; o.w = (1.0f - z.w) * n + z.w * hh.w;
    *(float4*)&out[off] = o;
}

// ---------------------------------------------------------------------------
extern "C" void kernel_launch(void* const* d_in, const int* in_sizes, int n_in,
                              void* d_out, int out_size)
{
    const float* x    = (const float*)d_in[0];
    const int*   ei   = (const int*)  d_in[1];
    const float* h    = (const float*)d_in[2];
    const float* W_xr = (const float*)d_in[3];
    const float* b_xr = (const float*)d_in[4];
    const float* W_hr = (const float*)d_in[5];
    const float* W_xz = (const float*)d_in[6];
    const float* b_xz = (const float*)d_in[7];
    const float* W_hz = (const float*)d_in[8];
    const float* W_l  = (const float*)d_in[9];
    const float* b_l  = (const float*)d_in[10];
    const float* W_r  = (const float*)d_in[11];
    float* out = (float*)d_out;

    const int gemm_grid = (NN + 127) / 128;   // 391

    prep_w<<<(KK * DH + 255) / 256, 256>>>(W_xr, W_hr, W_xz, W_hz, W_l, W_r);
    prep_xh<<<(NN * (DH / 4) + 255) / 256, 256>>>(x, h);

    gemm_tf32<0><<<gemm_grid, 256>>>(b_xr, h, NN);
    gemm_tf32<1><<<gemm_grid, 256>>>(b_xz, h, NN);
    gemm_tf32<2><<<gemm_grid, 256>>>(nullptr, h, NN);
    gemm_tf32<3><<<gemm_grid, 256>>>(nullptr, h, NN);

    scatter_kernel<<<(EE + 7) / 8, 256>>>(ei);

    final_kernel<<<(NN * (DH / 4) + 255) / 256, 256>>>(h, b_l, out);
}

// round 5
// speedup vs baseline: 2.0946x; 1.0017x over previous
#include <cuda_runtime.h>
#include <cstdint>

// Problem constants (fixed by the dataset)
#define NN 50000
#define DH 128
#define EE 800000
#define KK 256

// ---------------------------------------------------------------------------
// Scratch device globals. Referenced ONLY from device code (host-shadow bug!).
// ---------------------------------------------------------------------------
__device__ uint32_t g_x32 [NN * DH];     // tf32(x)
__device__ uint32_t g_h32 [NN * DH];     // tf32(h_prev)
__device__ uint32_t g_rh32[NN * DH];     // tf32(r * h_prev)
__device__ uint32_t g_WB  [4 * KK * DH]; // packed tf32 weights, one 256x128 per GEMM
__device__ float g_z  [NN * DH];
__device__ float g_y  [NN * DH];
__device__ float g_w  [NN * DH];
__device__ float g_agg[NN * DH];
__device__ float g_cnt[NN];

__device__ __forceinline__ float sigmoidf_(float v) {
    return 1.0f / (1.0f + __expf(-v));
}
__device__ __forceinline__ uint32_t f2tf32(float f) {
    uint32_t r;
    asm("cvt.rna.tf32.f32 %0, %1;" : "=r"(r) : "f"(f));
    return r;
}
__device__ __forceinline__ void cpasync16(uint32_t dst, const void* src, int sz) {
    asm volatile("cp.async.ca.shared.global [%0], [%1], 16, %2;"
                 :: "r"(dst), "l"(src), "r"(sz));
}
__device__ __forceinline__ void mma_tf32(float c[4], uint32_t a0, uint32_t a1,
                                         uint32_t a2, uint32_t a3,
                                         uint32_t b0, uint32_t b1) {
    asm volatile(
        "mma.sync.aligned.m16n8k8.row.col.f32.tf32.tf32.f32 "
        "{%0,%1,%2,%3}, {%4,%5,%6,%7}, {%8,%9}, {%0,%1,%2,%3};"
        : "+f"(c[0]), "+f"(c[1]), "+f"(c[2]), "+f"(c[3])
        : "r"(a0), "r"(a1), "r"(a2), "r"(a3), "r"(b0), "r"(b1));
}

// ---------------------------------------------------------------------------
// Prep: pack weights as tf32 into g_WB.
// ---------------------------------------------------------------------------
__global__ __launch_bounds__(256) void prep_w(
    const float* __restrict__ W_xr, const float* __restrict__ W_hr,
    const float* __restrict__ W_xz, const float* __restrict__ W_hz,
    const float* __restrict__ W_l,  const float* __restrict__ W_r)
{
    const int i = blockIdx.x * blockDim.x + threadIdx.x;  // over KK*DH = 32768
    if (i >= KK * DH) return;
    const int k = i / DH;
    const int n = i % DH;
    const int kl = (k & 127) * DH + n;
    g_WB[0 * KK * DH + i] = f2tf32(k < 128 ? W_xr[kl] : W_hr[kl]);
    g_WB[1 * KK * DH + i] = f2tf32(k < 128 ? W_xz[kl] : W_hz[kl]);
    g_WB[2 * KK * DH + i] = f2tf32(W_l[i]);
    g_WB[3 * KK * DH + i] = f2tf32(W_r[i]);
}

// Prep: convert x and h to tf32 (rna), also zero g_agg / g_cnt.
__global__ __launch_bounds__(256) void prep_xh(
    const float* __restrict__ x, const float* __restrict__ h)
{
    const int i = blockIdx.x * blockDim.x + threadIdx.x;  // over NN*DH/4
    if (i >= NN * (DH / 4)) return;
    const float4 xv = *(const float4*)&x[(size_t)i * 4];
    const float4 hv = *(const float4*)&h[(size_t)i * 4];
    uint4 xo, ho;
    xo.x = f2tf32(xv.x); xo.y = f2tf32(xv.y); xo.z = f2tf32(xv.z); xo.w = f2tf32(xv.w);
    ho.x = f2tf32(hv.x); ho.y = f2tf32(hv.y); ho.z = f2tf32(hv.z); ho.w = f2tf32(hv.w);
    *(uint4*)&g_x32[(size_t)i * 4] = xo;
    *(uint4*)&g_h32[(size_t)i * 4] = ho;
    *(float4*)&g_agg[(size_t)i * 4] = make_float4(0.f, 0.f, 0.f, 0.f);
    if (i < NN) g_cnt[i] = 0.0f;
}

// ---------------------------------------------------------------------------
// TF32 tensor-core GEMM: C[N,128] = Acat[N,256] @ B[256,128]
//   MODE 0: Acat=[x|h],  epi: rh = sigmoid(c+bias)*h -> g_rh32 (tf32)
//   MODE 1: Acat=[x|h],  epi: z  = sigmoid(c+bias)   -> g_z (f32)
//   MODE 2: Acat=[x|rh], epi: c -> g_y
//   MODE 3: Acat=[x|rh], epi: c -> g_w
// BM=128 BN=128 BK=16, 256 threads, warp tile 64x32.
// 3-stage cp.async pipeline, ONE __syncthreads per K-chunk.
// ---------------------------------------------------------------------------
#define AP 20    // As row pitch in words (bank-conflict-free)
#define BP 136   // Bs row pitch in words
#define ST 3     // pipeline stages

template <int MODE>
__global__ __launch_bounds__(256) void gemm_tf32(
    const float* __restrict__ bias, const float* __restrict__ hprev, int Nrows)
{
    __shared__ uint32_t As[ST][128 * AP];
    __shared__ uint32_t Bs[ST][16 * BP];

    const uint32_t* A0 = g_x32;
    const uint32_t* A1 = (MODE >= 2) ? g_rh32 : g_h32;
    const uint32_t* B  = g_WB + MODE * (KK * DH);

    const int tid  = threadIdx.x;
    const int lane = tid & 31;
    const int wid  = tid >> 5;
    const int row0 = blockIdx.x * 128;
    const int wm   = (wid >> 2) * 64;   // warp m offset (0 / 64)
    const int wn   = (wid & 3) * 32;    // warp n offset (0/32/64/96)
    const int g    = lane >> 2;         // 0..7
    const int t    = lane & 3;          // 0..3

    float acc[4][4][4];
#pragma unroll
    for (int mi = 0; mi < 4; mi++)
#pragma unroll
        for (int ni = 0; ni < 4; ni++)
#pragma unroll
            for (int q = 0; q < 4; q++) acc[mi][ni][q] = 0.0f;

    // staging: issue cp.async for K-chunk c into buffer buf, commit as a group
    auto stage = [&](int c, int buf) {
        const int k0 = c * 16;
        const uint32_t* Asrc = (k0 < 128) ? A0 : A1;
        const int ka = k0 & 127;
#pragma unroll
        for (int i = 0; i < 2; i++) {           // A: 128 rows x 16 = 512 float4
            const int id  = tid + i * 256;
            const int row = id >> 2;
            const int kq  = (id & 3) * 4;
            const uint32_t dst = (uint32_t)__cvta_generic_to_shared(
                &As[buf][row * AP + kq]);
            const int sz = (row0 + row < Nrows) ? 16 : 0;
            cpasync16(dst, &Asrc[(size_t)(row0 + row) * DH + ka + kq], sz);
        }
#pragma unroll
        for (int i = 0; i < 2; i++) {           // B: 16 rows x 128 = 512 float4
            const int id  = tid + i * 256;
            const int row = id >> 5;
            const int nq  = (id & 31) * 4;
            const uint32_t dst = (uint32_t)__cvta_generic_to_shared(
                &Bs[buf][row * BP + nq]);
            cpasync16(dst, &B[(size_t)(k0 + row) * DH + nq], 16);
        }
        asm volatile("cp.async.commit_group;");
    };

    // prologue: fill ST-1 stages
    stage(0, 0);
    stage(1, 1);

#pragma unroll 1
    for (int c = 0; c < 16; c++) {
        // wait for chunk c's group: while staging continues at most 1 younger
        // group may remain pending; on the last chunk drain fully.
        if (c < 15) {
            asm volatile("cp.async.wait_group %0;" :: "n"(1));
        } else {
            asm volatile("cp.async.wait_group %0;" :: "n"(0));
        }
        __syncthreads();   // also fences: chunk c-1 reads done -> buf (c+2)%ST free

        if (c + 2 < 16) stage(c + 2, (c + 2) % ST);

        const int buf = c % ST;
#pragma unroll
        for (int k8 = 0; k8 < 2; k8++) {
            const int kk = k8 * 8;
            uint32_t a[4][4], b[4][2];
#pragma unroll
            for (int mi = 0; mi < 4; mi++) {
                const int rb = wm + mi * 16 + g;
                a[mi][0] = As[buf][(rb)     * AP + kk + t];
                a[mi][1] = As[buf][(rb + 8) * AP + kk + t];
                a[mi][2] = As[buf][(rb)     * AP + kk + t + 4];
                a[mi][3] = As[buf][(rb + 8) * AP + kk + t + 4];
            }
#pragma unroll
            for (int ni = 0; ni < 4; ni++) {
                const int cb = wn + ni * 8 + g;
                b[ni][0] = Bs[buf][(kk + t)     * BP + cb];
                b[ni][1] = Bs[buf][(kk + t + 4) * BP + cb];
            }
#pragma unroll
            for (int mi = 0; mi < 4; mi++)
#pragma unroll
                for (int ni = 0; ni < 4; ni++)
                    mma_tf32(acc[mi][ni], a[mi][0], a[mi][1], a[mi][2], a[mi][3],
                             b[ni][0], b[ni][1]);
        }
    }

    // epilogue: thread owns (row = wm+mi*16+g(+8), cols = wn+ni*8+2t, +1)
#pragma unroll
    for (int mi = 0; mi < 4; mi++) {
#pragma unroll
        for (int half = 0; half < 2; half++) {
            const int grow = row0 + wm + mi * 16 + g + half * 8;
            if (grow >= Nrows) continue;
#pragma unroll
            for (int ni = 0; ni < 4; ni++) {
                const int col = wn + ni * 8 + 2 * t;
                float c0 = acc[mi][ni][half * 2 + 0];
                float c1 = acc[mi][ni][half * 2 + 1];
                const size_t off = (size_t)grow * DH + col;
                if (MODE == 0) {
                    c0 = sigmoidf_(c0 + bias[col]);
                    c1 = sigmoidf_(c1 + bias[col + 1]);
                    const float2 hh = *(const float2*)&hprev[off];
                    uint2 o;
                    o.x = f2tf32(c0 * hh.x);
                    o.y = f2tf32(c1 * hh.y);
                    *(uint2*)&g_rh32[off] = o;
                } else if (MODE == 1) {
                    float2 o;
                    o.x = sigmoidf_(c0 + bias[col]);
                    o.y = sigmoidf_(c1 + bias[col + 1]);
                    *(float2*)&g_z[off] = o;
                } else if (MODE == 2) {
                    *(float2*)&g_y[off] = make_float2(c0, c1);
                } else {
                    *(float2*)&g_w[off] = make_float2(c0, c1);
                }
            }
        }
    }
}

// ---------------------------------------------------------------------------
// Edge scatter: one warp per edge; lane l handles floats [4l, 4l+4).
// ---------------------------------------------------------------------------
__global__ __launch_bounds__(256) void scatter_kernel(const int* __restrict__ ei)
{
    const int warp = (blockIdx.x * blockDim.x + threadIdx.x) >> 5;
    const int lane = threadIdx.x & 31;
    if (warp >= EE) return;

    const int src = ei[warp];
    const int dst = ei[EE + warp];

    const float4 v = *(const float4*)&g_y[(size_t)src * DH + lane * 4];
    float* p = &g_agg[(size_t)dst * DH + lane * 4];
    asm volatile("red.global.add.v4.f32 [%0], {%1,%2,%3,%4};"
                 :: "l"(p), "f"(v.x), "f"(v.y), "f"(v.z), "f"(v.w)
                 : "memory");
    if (lane == 0) {
        asm volatile("red.global.add.f32 [%0], %1;"
                     :: "l"(&g_cnt[dst]), "f"(1.0f) : "memory");
    }
}

// ---------------------------------------------------------------------------
// Final: out = (1-z) * (agg/max(cnt,1) + b_l + w) + z * h_prev
// ---------------------------------------------------------------------------
__global__ __launch_bounds__(256) void final_kernel(
    const float* __restrict__ hprev, const float* __restrict__ b_l,
    float* __restrict__ out)
{
    const int i4 = blockIdx.x * blockDim.x + threadIdx.x;   // over NN*32
    if (i4 >= NN * (DH / 4)) return;
    const int node = i4 >> 5;
    const int c4   = i4 & 31;
    const size_t off = (size_t)i4 * 4;

    const float inv = 1.0f / fmaxf(g_cnt[node], 1.0f);
    const float4 a  = *(const float4*)&g_agg[off];
    const float4 w  = *(const float4*)&g_w[off];
    const float4 z  = *(const float4*)&g_z[off];
    const float4 hh = *(const float4*)&hprev[off];
    const float4 bl = *(const float4*)&b_l[c4 * 4];

    float4 o;
    float n;
    n = fmaf(a.x, inv, bl.x) + w.x; o.x = (1.0f - z.x) * n + z.x * hh.x;
    n = fmaf(a.y, inv, bl.y) + w.y; o.y = (1.0f - z.y) * n + z.y * hh.y;
    n = fmaf(a.z, inv, bl.z) + w.z; o.z = (1.0f - z.z) * n + z.z * hh.z;
    n = fmaf(a.w, inv, bl.w) + w.w; o.w = (1.0f - z.w) * n + z.w * hh.w;
    *(float4*)&out[off] = o;
}

// ---------------------------------------------------------------------------
extern "C" void kernel_launch(void* const* d_in, const int* in_sizes, int n_in,
                              void* d_out, int out_size)
{
    const float* x    = (const float*)d_in[0];
    const int*   ei   = (const int*)  d_in[1];
    const float* h    = (const float*)d_in[2];
    const float* W_xr = (const float*)d_in[3];
    const float* b_xr = (const float*)d_in[4];
    const float* W_hr = (const float*)d_in[5];
    const float* W_xz = (const float*)d_in[6];
    const float* b_xz = (const float*)d_in[7];
    const float* W_hz = (const float*)d_in[8];
    const float* W_l  = (const float*)d_in[9];
    const float* b_l  = (const float*)d_in[10];
    const float* W_r  = (const float*)d_in[11];
    float* out = (float*)d_out;

    const int gemm_grid = (NN + 127) / 128;   // 391

    prep_w<<<(KK * DH + 255) / 256, 256>>>(W_xr, W_hr, W_xz, W_hz, W_l, W_r);
    prep_xh<<<(NN * (DH / 4) + 255) / 256, 256>>>(x, h);

    gemm_tf32<0><<<gemm_grid, 256>>>(b_xr, h, NN);
    gemm_tf32<1><<<gemm_grid, 256>>>(b_xz, h, NN);
    gemm_tf32<2><<<gemm_grid, 256>>>(nullptr, h, NN);
    gemm_tf32<3><<<gemm_grid, 256>>>(nullptr, h, NN);

    scatter_kernel<<<(EE + 7) / 8, 256>>>(ei);

    final_kernel<<<(NN * (DH / 4) + 255) / 256, 256>>>(h, b_l, out);
}

// round 6
// speedup vs baseline: 2.1038x; 1.0044x over previous
#include <cuda_runtime.h>
#include <cstdint>

// Problem constants (fixed by the dataset)
#define NN 50000
#define DH 128
#define EE 800000
#define KK 256

// ---------------------------------------------------------------------------
// Scratch device globals. Referenced ONLY from device code (host-shadow bug!).
// A-side operands (x/h/rh) and weights are stored k-PAIR-PERMUTED:
//   within each 16-k group, order = 0,4,1,5,2,6,3,7, 8,12,9,13,10,14,11,15
// so an LDS.64 yields the (k, k+4) fragment pair directly.
// Weights additionally stored n-major: g_WB[mode][n][k_perm].
// ---------------------------------------------------------------------------
__device__ uint32_t g_x32 [NN * DH];
__device__ uint32_t g_h32 [NN * DH];
__device__ uint32_t g_rh32[NN * DH];
__device__ uint32_t g_WB  [4 * KK * DH];
__device__ float g_z  [NN * DH];
__device__ float g_y  [NN * DH];
__device__ float g_w  [NN * DH];
__device__ float g_agg[NN * DH];
__device__ float g_cnt[NN];

__device__ __forceinline__ float sigmoidf_(float v) {
    return 1.0f / (1.0f + __expf(-v));
}
__device__ __forceinline__ uint32_t f2tf32(float f) {
    uint32_t r;
    asm("cvt.rna.tf32.f32 %0, %1;" : "=r"(r) : "f"(f));
    return r;
}
// pair permutation within 16-k groups (upper bits pass through)
__device__ __forceinline__ int permk(int k) {
    return (k & ~15) | (k & 8) | ((k & 3) << 1) | ((k >> 2) & 1);
}
__device__ __forceinline__ void cpasync16(uint32_t dst, const void* src, int sz) {
    asm volatile("cp.async.ca.shared.global [%0], [%1], 16, %2;"
                 :: "r"(dst), "l"(src), "r"(sz));
}
__device__ __forceinline__ void mma_tf32(float c[4], uint32_t a0, uint32_t a1,
                                         uint32_t a2, uint32_t a3,
                                         uint32_t b0, uint32_t b1) {
    asm volatile(
        "mma.sync.aligned.m16n8k8.row.col.f32.tf32.tf32.f32 "
        "{%0,%1,%2,%3}, {%4,%5,%6,%7}, {%8,%9}, {%0,%1,%2,%3};"
        : "+f"(c[0]), "+f"(c[1]), "+f"(c[2]), "+f"(c[3])
        : "r"(a0), "r"(a1), "r"(a2), "r"(a3), "r"(b0), "r"(b1));
}

// ---------------------------------------------------------------------------
// Prep W: transpose to [mode][n][k_perm] tf32 via smem tile.
// grid (8 kb, 4 nb, 4 mode), block (32, 8).
// ---------------------------------------------------------------------------
__global__ void prep_w(
    const float* __restrict__ W_xr, const float* __restrict__ W_hr,
    const float* __restrict__ W_xz, const float* __restrict__ W_hz,
    const float* __restrict__ W_l,  const float* __restrict__ W_r)
{
    __shared__ float s[32][33];
    const int kb = blockIdx.x, nb = blockIdx.y, mode = blockIdx.z;
    const int tx = threadIdx.x, ty = threadIdx.y;

#pragma unroll
    for (int r = 0; r < 4; r++) {
        const int k = kb * 32 + ty + r * 8;
        const int n = nb * 32 + tx;
        float v;
        if (mode == 0)      v = (k < 128) ? W_xr[k * DH + n] : W_hr[(k - 128) * DH + n];
        else if (mode == 1) v = (k < 128) ? W_xz[k * DH + n] : W_hz[(k - 128) * DH + n];
        else if (mode == 2) v = W_l[k * DH + n];
        else                v = W_r[k * DH + n];
        s[ty + r * 8][tx] = v;
    }
    __syncthreads();
#pragma unroll
    for (int r = 0; r < 4; r++) {
        const int n = nb * 32 + ty + r * 8;
        const int k = kb * 32 + tx;
        g_WB[(size_t)mode * KK * DH + n * KK + permk(k)] = f2tf32(s[tx][ty + r * 8]);
    }
}

// Prep: tf32(x), tf32(h) with k-pair permutation; zero agg/cnt.
__global__ __launch_bounds__(256) void prep_xh(
    const float* __restrict__ x, const float* __restrict__ h)
{
    const int i = blockIdx.x * blockDim.x + threadIdx.x;  // over NN*DH/4
    if (i >= NN * (DH / 4)) return;
    const int node = i >> 5;
    const int k    = (i & 31) * 4;
    const size_t base = (size_t)node * DH;
    const float4 xv = *(const float4*)&x[(size_t)i * 4];
    const float4 hv = *(const float4*)&h[(size_t)i * 4];
    g_x32[base + permk(k + 0)] = f2tf32(xv.x);
    g_x32[base + permk(k + 1)] = f2tf32(xv.y);
    g_x32[base + permk(k + 2)] = f2tf32(xv.z);
    g_x32[base + permk(k + 3)] = f2tf32(xv.w);
    g_h32[base + permk(k + 0)] = f2tf32(hv.x);
    g_h32[base + permk(k + 1)] = f2tf32(hv.y);
    g_h32[base + permk(k + 2)] = f2tf32(hv.z);
    g_h32[base + permk(k + 3)] = f2tf32(hv.w);
    *(float4*)&g_agg[(size_t)i * 4] = make_float4(0.f, 0.f, 0.f, 0.f);
    if (i < NN) g_cnt[i] = 0.0f;
}

// ---------------------------------------------------------------------------
// TF32 tensor-core GEMM: C[N,128] = Acat[N,256] @ B[256,128]
// BM=128 BN=128 BK=16, 256 threads, warp tile 64x32.
// 3-stage cp.async pipeline + register fragment double-buffer, full unroll.
// ---------------------------------------------------------------------------
#define AP 24    // As row pitch (words): conflict-free LDS.64 per half-warp phase
#define BP 20    // Bs row pitch (words)
#define ST 3

template <int MODE>
__global__ __launch_bounds__(256, 2) void gemm_tf32(
    const float* __restrict__ bias, const float* __restrict__ hprev, int Nrows)
{
    __shared__ uint32_t As[ST][128 * AP];
    __shared__ uint32_t Bs[ST][128 * BP];

    const uint32_t* A0 = g_x32;
    const uint32_t* A1 = (MODE >= 2) ? g_rh32 : g_h32;
    const uint32_t* B  = g_WB + (size_t)MODE * (KK * DH);

    const int tid  = threadIdx.x;
    const int lane = tid & 31;
    const int wid  = tid >> 5;
    const int row0 = blockIdx.x * 128;
    const int wm   = (wid >> 2) * 64;
    const int wn   = (wid & 3) * 32;
    const int g    = lane >> 2;
    const int t    = lane & 3;

    float acc[4][4][4];
#pragma unroll
    for (int mi = 0; mi < 4; mi++)
#pragma unroll
        for (int ni = 0; ni < 4; ni++)
#pragma unroll
            for (int q = 0; q < 4; q++) acc[mi][ni][q] = 0.0f;

    // stage K-chunk c into buffer buf
    auto stage = [&](int c, int buf) {
        const int k0 = c * 16;
        const uint32_t* Asrc = (k0 < 128) ? A0 : A1;
        const int ka = k0 & 127;
#pragma unroll
        for (int i = 0; i < 2; i++) {          // A: 128 rows x 16 words
            const int id  = tid + i * 256;
            const int row = id >> 2;
            const int kq  = (id & 3) * 4;
            const uint32_t dst = (uint32_t)__cvta_generic_to_shared(
                &As[buf][row * AP + kq]);
            const int sz = (row0 + row < Nrows) ? 16 : 0;
            cpasync16(dst, &Asrc[(size_t)(row0 + row) * DH + ka + kq], sz);
        }
#pragma unroll
        for (int i = 0; i < 2; i++) {          // B: 128 n-rows x 16 words
            const int id = tid + i * 256;
            const int n  = id >> 2;
            const int kq = (id & 3) * 4;
            const uint32_t dst = (uint32_t)__cvta_generic_to_shared(
                &Bs[buf][n * BP + kq]);
            cpasync16(dst, &B[(size_t)n * KK + k0 + kq], 16);
        }
        asm volatile("cp.async.commit_group;");
    };

    uint32_t fa0[4][4], fb0[4][2], fa1[4][4], fb1[4][2];

    auto ldA = [&](uint32_t (&a)[4][4], int buf, int k8) {
#pragma unroll
        for (int mi = 0; mi < 4; mi++) {
            const int rb = wm + mi * 16 + g;
            const uint2 lo = *(const uint2*)&As[buf][rb * AP + k8 * 8 + 2 * t];
            const uint2 hi = *(const uint2*)&As[buf][(rb + 8) * AP + k8 * 8 + 2 * t];
            a[mi][0] = lo.x; a[mi][1] = hi.x; a[mi][2] = lo.y; a[mi][3] = hi.y;
        }
    };
    auto ldB = [&](uint32_t (&b)[4][2], int buf, int k8) {
#pragma unroll
        for (int ni = 0; ni < 4; ni++) {
            const int cb = wn + ni * 8 + g;
            const uint2 v = *(const uint2*)&Bs[buf][cb * BP + k8 * 8 + 2 * t];
            b[ni][0] = v.x; b[ni][1] = v.y;
        }
    };
    auto domma = [&](uint32_t (&a)[4][4], uint32_t (&b)[4][2]) {
#pragma unroll
        for (int mi = 0; mi < 4; mi++)
#pragma unroll
            for (int ni = 0; ni < 4; ni++)
                mma_tf32(acc[mi][ni], a[mi][0], a[mi][1], a[mi][2], a[mi][3],
                         b[ni][0], b[ni][1]);
    };

    // prologue
    stage(0, 0);
    stage(1, 1);
    asm volatile("cp.async.wait_group 1;");   // chunk 0 arrived
    __syncthreads();
    ldA(fa0, 0, 0); ldB(fb0, 0, 0);

#pragma unroll
    for (int c = 0; c < 16; c++) {
        const int buf = c % ST;
        if (c + 2 < 16) stage(c + 2, (c + 2) % ST);
        ldA(fa1, buf, 1); ldB(fb1, buf, 1);
        domma(fa0, fb0);
        if (c < 15) {
            if (c < 14) { asm volatile("cp.async.wait_group 1;"); }
            else        { asm volatile("cp.async.wait_group 0;"); }
            __syncthreads();
            ldA(fa0, (c + 1) % ST, 0); ldB(fb0, (c + 1) % ST, 0);
        }
        domma(fa1, fb1);
    }

    // epilogue: thread owns (row = wm+mi*16+g(+8), cols = wn+ni*8+2t, +1)
#pragma unroll
    for (int mi = 0; mi < 4; mi++) {
#pragma unroll
        for (int half = 0; half < 2; half++) {
            const int grow = row0 + wm + mi * 16 + g + half * 8;
            if (grow >= Nrows) continue;
#pragma unroll
            for (int ni = 0; ni < 4; ni++) {
                const int col = wn + ni * 8 + 2 * t;
                float c0 = acc[mi][ni][half * 2 + 0];
                float c1 = acc[mi][ni][half * 2 + 1];
                const size_t off = (size_t)grow * DH + col;
                if (MODE == 0) {
                    c0 = sigmoidf_(c0 + bias[col]);
                    c1 = sigmoidf_(c1 + bias[col + 1]);
                    const float2 hh = *(const float2*)&hprev[off];
                    const size_t rbase = (size_t)grow * DH;
                    g_rh32[rbase + permk(col)]     = f2tf32(c0 * hh.x);
                    g_rh32[rbase + permk(col + 1)] = f2tf32(c1 * hh.y);
                } else if (MODE == 1) {
                    float2 o;
                    o.x = sigmoidf_(c0 + bias[col]);
                    o.y = sigmoidf_(c1 + bias[col + 1]);
                    *(float2*)&g_z[off] = o;
                } else if (MODE == 2) {
                    *(float2*)&g_y[off] = make_float2(c0, c1);
                } else {
                    *(float2*)&g_w[off] = make_float2(c0, c1);
                }
            }
        }
    }
}

// ---------------------------------------------------------------------------
// Edge scatter: one warp per edge; lane l handles floats [4l, 4l+4).
// ---------------------------------------------------------------------------
__global__ __launch_bounds__(256) void scatter_kernel(const int* __restrict__ ei)
{
    const int warp = (blockIdx.x * blockDim.x + threadIdx.x) >> 5;
    const int lane = threadIdx.x & 31;
    if (warp >= EE) return;

    const int src = ei[warp];
    const int dst = ei[EE + warp];

    const float4 v = *(const float4*)&g_y[(size_t)src * DH + lane * 4];
    float* p = &g_agg[(size_t)dst * DH + lane * 4];
    asm volatile("red.global.add.v4.f32 [%0], {%1,%2,%3,%4};"
                 :: "l"(p), "f"(v.x), "f"(v.y), "f"(v.z), "f"(v.w)
                 : "memory");
    if (lane == 0) {
        asm volatile("red.global.add.f32 [%0], %1;"
                     :: "l"(&g_cnt[dst]), "f"(1.0f) : "memory");
    }
}

// ---------------------------------------------------------------------------
// Final: out = (1-z) * (agg/max(cnt,1) + b_l + w) + z * h_prev
// ---------------------------------------------------------------------------
__global__ __launch_bounds__(256) void final_kernel(
    const float* __restrict__ hprev, const float* __restrict__ b_l,
    float* __restrict__ out)
{
    const int i4 = blockIdx.x * blockDim.x + threadIdx.x;   // over NN*32
    if (i4 >= NN * (DH / 4)) return;
    const int node = i4 >> 5;
    const int c4   = i4 & 31;
    const size_t off = (size_t)i4 * 4;

    const float inv = 1.0f / fmaxf(g_cnt[node], 1.0f);
    const float4 a  = *(const float4*)&g_agg[off];
    const float4 w  = *(const float4*)&g_w[off];
    const float4 z  = *(const float4*)&g_z[off];
    const float4 hh = *(const float4*)&hprev[off];
    const float4 bl = *(const float4*)&b_l[c4 * 4];

    float4 o;
    float n;
    n = fmaf(a.x, inv, bl.x) + w.x; o.x = (1.0f - z.x) * n + z.x * hh.x;
    n = fmaf(a.y, inv, bl.y) + w.y; o.y = (1.0f - z.y) * n + z.y * hh.y;
    n = fmaf(a.z, inv, bl.z) + w.z; o.z = (1.0f - z.z) * n + z.z * hh.z;
    n = fmaf(a.w, inv, bl.w) + w.w; o.w = (1.0f - z.w) * n + z.w * hh.w;
    *(float4*)&out[off] = o;
}

// ---------------------------------------------------------------------------
extern "C" void kernel_launch(void* const* d_in, const int* in_sizes, int n_in,
                              void* d_out, int out_size)
{
    const float* x    = (const float*)d_in[0];
    const int*   ei   = (const int*)  d_in[1];
    const float* h    = (const float*)d_in[2];
    const float* W_xr = (const float*)d_in[3];
    const float* b_xr = (const float*)d_in[4];
    const float* W_hr = (const float*)d_in[5];
    const float* W_xz = (const float*)d_in[6];
    const float* b_xz = (const float*)d_in[7];
    const float* W_hz = (const float*)d_in[8];
    const float* W_l  = (const float*)d_in[9];
    const float* b_l  = (const float*)d_in[10];
    const float* W_r  = (const float*)d_in[11];
    float* out = (float*)d_out;

    const int gemm_grid = (NN + 127) / 128;   // 391

    prep_w<<<dim3(8, 4, 4), dim3(32, 8)>>>(W_xr, W_hr, W_xz, W_hz, W_l, W_r);
    prep_xh<<<(NN * (DH / 4) + 255) / 256, 256>>>(x, h);

    gemm_tf32<0><<<gemm_grid, 256>>>(b_xr, h, NN);
    gemm_tf32<1><<<gemm_grid, 256>>>(b_xz, h, NN);
    gemm_tf32<2><<<gemm_grid, 256>>>(nullptr, h, NN);
    gemm_tf32<3><<<gemm_grid, 256>>>(nullptr, h, NN);

    scatter_kernel<<<(EE + 7) / 8, 256>>>(ei);

    final_kernel<<<(NN * (DH / 4) + 255) / 256, 256>>>(h, b_l, out);
}

// round 8
// speedup vs baseline: 2.8178x; 1.3394x over previous
#include <cuda_runtime.h>
#include <cstdint>

// Problem constants (fixed by the dataset)
#define NN 50000
#define DH 128
#define EE 800000
#define KK 256

// ---------------------------------------------------------------------------
// Scratch device globals. Referenced ONLY from device code (host-shadow bug!).
// A-side operands and weights stored k-PAIR-PERMUTED (see permk) so LDS.64
// yields the (k, k+4) mma fragment pair. Weights n-major: g_WB[mode][n][k].
// ---------------------------------------------------------------------------
__device__ uint32_t g_x32 [NN * DH];
__device__ uint32_t g_h32 [NN * DH];
__device__ uint32_t g_rh32[NN * DH];
__device__ uint32_t g_WB  [4 * KK * DH];
__device__ float g_z  [NN * DH];
__device__ float g_y  [NN * DH];
__device__ float g_w  [NN * DH];
// CSR for gather
__device__ int g_deg[NN];
__device__ int g_cur[NN];
__device__ int g_off[NN];
__device__ int g_csr[EE];

__device__ __forceinline__ float sigmoidf_(float v) {
    return 1.0f / (1.0f + __expf(-v));
}
__device__ __forceinline__ uint32_t f2tf32(float f) {
    uint32_t r;
    asm("cvt.rna.tf32.f32 %0, %1;" : "=r"(r) : "f"(f));
    return r;
}
__device__ __forceinline__ int permk(int k) {
    return (k & ~15) | (k & 8) | ((k & 3) << 1) | ((k >> 2) & 1);
}
__device__ __forceinline__ void cpasync16(uint32_t dst, const void* src, int sz) {
    asm volatile("cp.async.ca.shared.global [%0], [%1], 16, %2;"
                 :: "r"(dst), "l"(src), "r"(sz));
}
__device__ __forceinline__ void mma_tf32(float c[4], uint32_t a0, uint32_t a1,
                                         uint32_t a2, uint32_t a3,
                                         uint32_t b0, uint32_t b1) {
    asm volatile(
        "mma.sync.aligned.m16n8k8.row.col.f32.tf32.tf32.f32 "
        "{%0,%1,%2,%3}, {%4,%5,%6,%7}, {%8,%9}, {%0,%1,%2,%3};"
        : "+f"(c[0]), "+f"(c[1]), "+f"(c[2]), "+f"(c[3])
        : "r"(a0), "r"(a1), "r"(a2), "r"(a3), "r"(b0), "r"(b1));
}

// ---------------------------------------------------------------------------
// Prep W: transpose to [mode][n][k_perm] tf32 via smem tile.
// ---------------------------------------------------------------------------
__global__ void prep_w(
    const float* __restrict__ W_xr, const float* __restrict__ W_hr,
    const float* __restrict__ W_xz, const float* __restrict__ W_hz,
    const float* __restrict__ W_l,  const float* __restrict__ W_r)
{
    __shared__ float s[32][33];
    const int kb = blockIdx.x, nb = blockIdx.y, mode = blockIdx.z;
    const int tx = threadIdx.x, ty = threadIdx.y;

#pragma unroll
    for (int r = 0; r < 4; r++) {
        const int k = kb * 32 + ty + r * 8;
        const int n = nb * 32 + tx;
        float v;
        if (mode == 0)      v = (k < 128) ? W_xr[k * DH + n] : W_hr[(k - 128) * DH + n];
        else if (mode == 1) v = (k < 128) ? W_xz[k * DH + n] : W_hz[(k - 128) * DH + n];
        else if (mode == 2) v = W_l[k * DH + n];
        else                v = W_r[k * DH + n];
        s[ty + r * 8][tx] = v;
    }
    __syncthreads();
#pragma unroll
    for (int r = 0; r < 4; r++) {
        const int n = nb * 32 + ty + r * 8;
        const int k = kb * 32 + tx;
        g_WB[(size_t)mode * KK * DH + n * KK + permk(k)] = f2tf32(s[tx][ty + r * 8]);
    }
}

// Prep: tf32(x), tf32(h) with k-pair permutation.
__global__ __launch_bounds__(256) void prep_xh(
    const float* __restrict__ x, const float* __restrict__ h)
{
    const int i = blockIdx.x * blockDim.x + threadIdx.x;  // over NN*DH/4
    if (i >= NN * (DH / 4)) return;
    const int node = i >> 5;
    const int k    = (i & 31) * 4;
    const size_t base = (size_t)node * DH;
    const float4 xv = *(const float4*)&x[(size_t)i * 4];
    const float4 hv = *(const float4*)&h[(size_t)i * 4];
    g_x32[base + permk(k + 0)] = f2tf32(xv.x);
    g_x32[base + permk(k + 1)] = f2tf32(xv.y);
    g_x32[base + permk(k + 2)] = f2tf32(xv.z);
    g_x32[base + permk(k + 3)] = f2tf32(xv.w);
    g_h32[base + permk(k + 0)] = f2tf32(hv.x);
    g_h32[base + permk(k + 1)] = f2tf32(hv.y);
    g_h32[base + permk(k + 2)] = f2tf32(hv.z);
    g_h32[base + permk(k + 3)] = f2tf32(hv.w);
}

// ---------------------------------------------------------------------------
// CSR build: zero -> histogram -> single-block scan -> bucket fill
// ---------------------------------------------------------------------------
__global__ __launch_bounds__(256) void zero_dc()
{
    const int i = blockIdx.x * blockDim.x + threadIdx.x;
    if (i < NN) { g_deg[i] = 0; g_cur[i] = 0; }
}
__global__ __launch_bounds__(256) void hist_kernel(const int* __restrict__ ei)
{
    const int i = blockIdx.x * blockDim.x + threadIdx.x;
    if (i < EE) atomicAdd(&g_deg[ei[EE + i]], 1);
}
__global__ __launch_bounds__(1024) void scan_kernel()
{
    __shared__ int part[1024];
    const int t = threadIdx.x;
    const int CH = (NN + 1023) / 1024;   // 49
    const int base = t * CH;
    int s = 0;
    for (int i = 0; i < CH; i++) {
        const int idx = base + i;
        if (idx < NN) s += g_deg[idx];
    }
    part[t] = s;
    __syncthreads();
    // Hillis-Steele inclusive scan
    for (int d = 1; d < 1024; d <<= 1) {
        int v = (t >= d) ? part[t - d] : 0;
        __syncthreads();
        part[t] += v;
        __syncthreads();
    }
    int run = (t == 0) ? 0 : part[t - 1];
    for (int i = 0; i < CH; i++) {
        const int idx = base + i;
        if (idx < NN) { g_off[idx] = run; run += g_deg[idx]; }
    }
}
__global__ __launch_bounds__(256) void fill_kernel(const int* __restrict__ ei)
{
    const int i = blockIdx.x * blockDim.x + threadIdx.x;
    if (i >= EE) return;
    const int dst = ei[EE + i];
    const int pos = atomicAdd(&g_cur[dst], 1);
    g_csr[g_off[dst] + pos] = ei[i];
}

// ---------------------------------------------------------------------------
// TF32 tensor-core GEMM (unchanged from round 6 — known good).
// ---------------------------------------------------------------------------
#define AP 24
#define BP 20
#define ST 3

template <int MODE>
__global__ __launch_bounds__(256, 2) void gemm_tf32(
    const float* __restrict__ bias, const float* __restrict__ hprev, int Nrows)
{
    __shared__ uint32_t As[ST][128 * AP];
    __shared__ uint32_t Bs[ST][128 * BP];

    const uint32_t* A0 = g_x32;
    const uint32_t* A1 = (MODE >= 2) ? g_rh32 : g_h32;
    const uint32_t* B  = g_WB + (size_t)MODE * (KK * DH);

    const int tid  = threadIdx.x;
    const int lane = tid & 31;
    const int wid  = tid >> 5;
    const int row0 = blockIdx.x * 128;
    const int wm   = (wid >> 2) * 64;
    const int wn   = (wid & 3) * 32;
    const int g    = lane >> 2;
    const int t    = lane & 3;

    float acc[4][4][4];
#pragma unroll
    for (int mi = 0; mi < 4; mi++)
#pragma unroll
        for (int ni = 0; ni < 4; ni++)
#pragma unroll
            for (int q = 0; q < 4; q++) acc[mi][ni][q] = 0.0f;

    auto stage = [&](int c, int buf) {
        const int k0 = c * 16;
        const uint32_t* Asrc = (k0 < 128) ? A0 : A1;
        const int ka = k0 & 127;
#pragma unroll
        for (int i = 0; i < 2; i++) {
            const int id  = tid + i * 256;
            const int row = id >> 2;
            const int kq  = (id & 3) * 4;
            const uint32_t dst = (uint32_t)__cvta_generic_to_shared(
                &As[buf][row * AP + kq]);
            const int sz = (row0 + row < Nrows) ? 16 : 0;
            cpasync16(dst, &Asrc[(size_t)(row0 + row) * DH + ka + kq], sz);
        }
#pragma unroll
        for (int i = 0; i < 2; i++) {
            const int id = tid + i * 256;
            const int n  = id >> 2;
            const int kq = (id & 3) * 4;
            const uint32_t dst = (uint32_t)__cvta_generic_to_shared(
                &Bs[buf][n * BP + kq]);
            cpasync16(dst, &B[(size_t)n * KK + k0 + kq], 16);
        }
        asm volatile("cp.async.commit_group;");
    };

    uint32_t fa0[4][4], fb0[4][2], fa1[4][4], fb1[4][2];

    auto ldA = [&](uint32_t (&a)[4][4], int buf, int k8) {
#pragma unroll
        for (int mi = 0; mi < 4; mi++) {
            const int rb = wm + mi * 16 + g;
            const uint2 lo = *(const uint2*)&As[buf][rb * AP + k8 * 8 + 2 * t];
            const uint2 hi = *(const uint2*)&As[buf][(rb + 8) * AP + k8 * 8 + 2 * t];
            a[mi][0] = lo.x; a[mi][1] = hi.x; a[mi][2] = lo.y; a[mi][3] = hi.y;
        }
    };
    auto ldB = [&](uint32_t (&b)[4][2], int buf, int k8) {
#pragma unroll
        for (int ni = 0; ni < 4; ni++) {
            const int cb = wn + ni * 8 + g;
            const uint2 v = *(const uint2*)&Bs[buf][cb * BP + k8 * 8 + 2 * t];
            b[ni][0] = v.x; b[ni][1] = v.y;
        }
    };
    auto domma = [&](uint32_t (&a)[4][4], uint32_t (&b)[4][2]) {
#pragma unroll
        for (int mi = 0; mi < 4; mi++)
#pragma unroll
            for (int ni = 0; ni < 4; ni++)
                mma_tf32(acc[mi][ni], a[mi][0], a[mi][1], a[mi][2], a[mi][3],
                         b[ni][0], b[ni][1]);
    };

    stage(0, 0);
    stage(1, 1);
    asm volatile("cp.async.wait_group 1;");
    __syncthreads();
    ldA(fa0, 0, 0); ldB(fb0, 0, 0);

#pragma unroll
    for (int c = 0; c < 16; c++) {
        const int buf = c % ST;
        if (c + 2 < 16) stage(c + 2, (c + 2) % ST);
        ldA(fa1, buf, 1); ldB(fb1, buf, 1);
        domma(fa0, fb0);
        if (c < 15) {
            if (c < 14) { asm volatile("cp.async.wait_group 1;"); }
            else        { asm volatile("cp.async.wait_group 0;"); }
            __syncthreads();
            ldA(fa0, (c + 1) % ST, 0); ldB(fb0, (c + 1) % ST, 0);
        }
        domma(fa1, fb1);
    }

#pragma unroll
    for (int mi = 0; mi < 4; mi++) {
#pragma unroll
        for (int half = 0; half < 2; half++) {
            const int grow = row0 + wm + mi * 16 + g + half * 8;
            if (grow >= Nrows) continue;
#pragma unroll
            for (int ni = 0; ni < 4; ni++) {
                const int col = wn + ni * 8 + 2 * t;
                float c0 = acc[mi][ni][half * 2 + 0];
                float c1 = acc[mi][ni][half * 2 + 1];
                const size_t off = (size_t)grow * DH + col;
                if (MODE == 0) {
                    c0 = sigmoidf_(c0 + bias[col]);
                    c1 = sigmoidf_(c1 + bias[col + 1]);
                    const float2 hh = *(const float2*)&hprev[off];
                    const size_t rbase = (size_t)grow * DH;
                    g_rh32[rbase + permk(col)]     = f2tf32(c0 * hh.x);
                    g_rh32[rbase + permk(col + 1)] = f2tf32(c1 * hh.y);
                } else if (MODE == 1) {
                    float2 o;
                    o.x = sigmoidf_(c0 + bias[col]);
                    o.y = sigmoidf_(c1 + bias[col + 1]);
                    *(float2*)&g_z[off] = o;
                } else if (MODE == 2) {
                    *(float2*)&g_y[off] = make_float2(c0, c1);
                } else {
                    *(float2*)&g_w[off] = make_float2(c0, c1);
                }
            }
        }
    }
}

// ---------------------------------------------------------------------------
// Gather + final fused: one warp per node.
// out = (1-z) * (sum_nbr(y)/max(deg,1) + b_l + w) + z * h_prev
// ---------------------------------------------------------------------------
__global__ __launch_bounds__(256) void gather_final(
    const float* __restrict__ hprev, const float* __restrict__ b_l,
    float* __restrict__ out)
{
    const int node = (blockIdx.x * blockDim.x + threadIdx.x) >> 5;
    const int lane = threadIdx.x & 31;
    if (node >= NN) return;

    const int off = g_off[node];
    const int deg = g_deg[node];

    float4 acc = make_float4(0.f, 0.f, 0.f, 0.f);
    int e = 0;
    for (; e + 4 <= deg; e += 4) {
        const int s0 = g_csr[off + e + 0];
        const int s1 = g_csr[off + e + 1];
        const int s2 = g_csr[off + e + 2];
        const int s3 = g_csr[off + e + 3];
        const float4 v0 = *(const float4*)&g_y[(size_t)s0 * DH + lane * 4];
        const float4 v1 = *(const float4*)&g_y[(size_t)s1 * DH + lane * 4];
        const float4 v2 = *(const float4*)&g_y[(size_t)s2 * DH + lane * 4];
        const float4 v3 = *(const float4*)&g_y[(size_t)s3 * DH + lane * 4];
        acc.x += (v0.x + v1.x) + (v2.x + v3.x);
        acc.y += (v0.y + v1.y) + (v2.y + v3.y);
        acc.z += (v0.z + v1.z) + (v2.z + v3.z);
        acc.w += (v0.w + v1.w) + (v2.w + v3.w);
    }
    for (; e < deg; e++) {
        const int s0 = g_csr[off + e];
        const float4 v0 = *(const float4*)&g_y[(size_t)s0 * DH + lane * 4];
        acc.x += v0.x; acc.y += v0.y; acc.z += v0.z; acc.w += v0.w;
    }

    const float inv = 1.0f / (float)max(deg, 1);
    const size_t o = (size_t)node * DH + lane * 4;
    const float4 w  = *(const float4*)&g_w[o];
    const float4 z  = *(const float4*)&g_z[o];
    const float4 hh = *(const float4*)&hprev[o];
    const float4 bl = *(const float4*)&b_l[lane * 4];

    float4 r;
    float n;
    n = fmaf(acc.x, inv, bl.x) + w.x; r.x = (1.0f - z.x) * n + z.x * hh.x;
    n = fmaf(acc.y, inv, bl.y) + w.y; r.y = (1.0f - z.y) * n + z.y * hh.y;
    n = fmaf(acc.z, inv, bl.z) + w.z; r.z = (1.0f - z.z) * n + z.z * hh.z;
    n = fmaf(acc.w, inv, bl.w) + w.w; r.w = (1.0f - z.w) * n + z.w * hh.w;
    *(float4*)&out[o] = r;
}

// ---------------------------------------------------------------------------
extern "C" void kernel_launch(void* const* d_in, const int* in_sizes, int n_in,
                              void* d_out, int out_size)
{
    const float* x    = (const float*)d_in[0];
    const int*   ei   = (const int*)  d_in[1];
    const float* h    = (const float*)d_in[2];
    const float* W_xr = (const float*)d_in[3];
    const float* b_xr = (const float*)d_in[4];
    const float* W_hr = (const float*)d_in[5];
    const float* W_xz = (const float*)d_in[6];
    const float* b_xz = (const float*)d_in[7];
    const float* W_hz = (const float*)d_in[8];
    const float* W_l  = (const float*)d_in[9];
    const float* b_l  = (const float*)d_in[10];
    const float* W_r  = (const float*)d_in[11];
    float* out = (float*)d_out;

    const int gemm_grid = (NN + 127) / 128;   // 391

    // One-time resources (created on the first, non-captured, call)
    static cudaStream_t sB = nullptr, sC = nullptr;
    static cudaEvent_t evRoot, evA, evG0, evB3, evC;
    if (!sB) {
        cudaStreamCreateWithFlags(&sB, cudaStreamNonBlocking);
        cudaStreamCreateWithFlags(&sC, cudaStreamNonBlocking);
        cudaEventCreateWithFlags(&evRoot, cudaEventDisableTiming);
        cudaEventCreateWithFlags(&evA,    cudaEventDisableTiming);
        cudaEventCreateWithFlags(&evG0,   cudaEventDisableTiming);
        cudaEventCreateWithFlags(&evB3,   cudaEventDisableTiming);
        cudaEventCreateWithFlags(&evC,    cudaEventDisableTiming);
    }

    // Fork point
    cudaEventRecord(evRoot, 0);

    // --- Stream C: CSR build (independent of GEMMs) ---
    cudaStreamWaitEvent(sC, evRoot, 0);
    zero_dc<<<(NN + 255) / 256, 256, 0, sC>>>();
    hist_kernel<<<(EE + 255) / 256, 256, 0, sC>>>(ei);
    scan_kernel<<<1, 1024, 0, sC>>>();
    fill_kernel<<<(EE + 255) / 256, 256, 0, sC>>>(ei);
    cudaEventRecord(evC, sC);

    // --- Main stream: preps ---
    prep_w<<<dim3(8, 4, 4), dim3(32, 8)>>>(W_xr, W_hr, W_xz, W_hz, W_l, W_r);
    prep_xh<<<(NN * (DH / 4) + 255) / 256, 256>>>(x, h);
    cudaEventRecord(evA, 0);

    // --- Stream B: z-gate GEMM (independent of r-gate chain) ---
    cudaStreamWaitEvent(sB, evA, 0);
    gemm_tf32<1><<<gemm_grid, 256, 0, sB>>>(b_xz, h, NN);

    // --- Main stream: r-gate, then y ---
    gemm_tf32<0><<<gemm_grid, 256>>>(b_xr, h, NN);
    cudaEventRecord(evG0, 0);

    // --- Stream B: w (needs rh from g0) ---
    cudaStreamWaitEvent(sB, evG0, 0);
    gemm_tf32<3><<<gemm_grid, 256, 0, sB>>>(nullptr, h, NN);
    cudaEventRecord(evB3, sB);

    gemm_tf32<2><<<gemm_grid, 256>>>(nullptr, h, NN);

    // --- Join: gather+final needs y (main), z & w (sB), CSR (sC) ---
    cudaStreamWaitEvent(0, evB3, 0);
    cudaStreamWaitEvent(0, evC, 0);
    gather_final<<<(NN * 32 + 255) / 256, 256>>>(h, b_l, out);
}